// round 1
// baseline (speedup 1.0000x reference)
#include <cuda_runtime.h>
#include <cuda_bf16.h>
#include <cstdint>

#define DEV __device__ __forceinline__

// problem dims
#define N_IMG 256
#define D_INF 768
#define D_HID 768
#define D_OUTF 512
#define M_GAL 100000
#define TOPK 5

// gemm tile
#define BM 128
#define BN 64
#define BK 32
#define AST 40   // bf16 row stride (80B, 16B-aligned, conflict-free for ldmatrix)
#define BST 40
#define BFST 36  // f32 staging row stride (144B)

struct alignas(16) Buf {
  __nv_bfloat16 Ahi[BM*AST];
  __nv_bfloat16 Alo[BM*AST];
  float         Bf [BN*BFST];
  __nv_bfloat16 Bhi[BN*BST];
  __nv_bfloat16 Blo[BN*BST];
};

// scratch (no cudaMalloc allowed)
__device__ __nv_bfloat16 g_Ahi1[N_IMG*D_INF];
__device__ __nv_bfloat16 g_Alo1[N_IMG*D_INF];
__device__ float         g_H   [N_IMG*D_HID];
__device__ __nv_bfloat16 g_Ahi2[N_IMG*D_HID];
__device__ __nv_bfloat16 g_Alo2[N_IMG*D_HID];
__device__ float         g_IMG [N_IMG*D_OUTF];
__device__ __nv_bfloat16 g_AhiN[N_IMG*D_OUTF];
__device__ __nv_bfloat16 g_AloN[N_IMG*D_OUTF];

DEV void cp16(void* s, const void* g){
  uint32_t sa = (uint32_t)__cvta_generic_to_shared(s);
  asm volatile("cp.async.cg.shared.global [%0], [%1], 16;" :: "r"(sa), "l"(g));
}
DEV void cp_commit(){ asm volatile("cp.async.commit_group;"); }
template<int W> DEV void cp_wait(){ asm volatile("cp.async.wait_group %0;" :: "n"(W)); }

DEV void ldsm4(uint32_t* d, const void* p){
  uint32_t a=(uint32_t)__cvta_generic_to_shared(p);
  asm volatile("ldmatrix.sync.aligned.m8n8.x4.shared.b16 {%0,%1,%2,%3}, [%4];"
    : "=r"(d[0]),"=r"(d[1]),"=r"(d[2]),"=r"(d[3]) : "r"(a));
}
DEV void ldsm2(uint32_t* d, const void* p){
  uint32_t a=(uint32_t)__cvta_generic_to_shared(p);
  asm volatile("ldmatrix.sync.aligned.m8n8.x2.shared.b16 {%0,%1}, [%2];"
    : "=r"(d[0]),"=r"(d[1]) : "r"(a));
}
DEV void mma_bf16(float* c, const uint32_t* a, const uint32_t* b){
  asm volatile("mma.sync.aligned.m16n8k16.row.col.f32.bf16.bf16.f32 "
    "{%0,%1,%2,%3}, {%4,%5,%6,%7}, {%8,%9}, {%0,%1,%2,%3};"
    : "+f"(c[0]),"+f"(c[1]),"+f"(c[2]),"+f"(c[3])
    : "r"(a[0]),"r"(a[1]),"r"(a[2]),"r"(a[3]),"r"(b[0]),"r"(b[1]));
}

DEV void load_chunk(Buf& b, const __nv_bfloat16* Ahi, const __nv_bfloat16* Alo,
                    const float* B, int m0, int n0, int k0, int K, int N, int tid){
  // A hi/lo: 128x32 bf16 each = 512 x 16B chunks; 2 per thread
#pragma unroll
  for (int c=0;c<2;c++){
    int ch = tid*2 + c;
    int r = ch >> 2, cg = (ch & 3) * 8;
    size_t go = (size_t)(m0 + r) * K + k0 + cg;
    cp16(&b.Ahi[r*AST + cg], Ahi + go);
    cp16(&b.Alo[r*AST + cg], Alo + go);
  }
  // B f32: 64x32 f32 = 512 x 16B chunks; 2 per thread. Clamp OOB rows (results discarded).
#pragma unroll
  for (int c=0;c<2;c++){
    int ch = tid*2 + c;
    int r = ch >> 3, cg = (ch & 7) * 4;
    int n = n0 + r; if (n > N-1) n = N-1;
    cp16(&b.Bf[r*BFST + cg], B + (size_t)n*K + k0 + cg);
  }
}

// C[M,N] = A[M,K] * B[N,K]^T with A pre-split to bf16 hi/lo, B split on the fly.
// 3-term bf16 split accumulation: hi*hi + hi*lo + lo*hi (fp32 accum).
template<bool BIAS, bool RELU>
__global__ __launch_bounds__(256, 2)
void gemm3s(const __nv_bfloat16* __restrict__ Ahi, const __nv_bfloat16* __restrict__ Alo,
            const float* __restrict__ B, const float* __restrict__ bias,
            float* __restrict__ C, int N, int K){
  extern __shared__ char raw[];
  Buf* bufs = reinterpret_cast<Buf*>(raw);
  const int tid = threadIdx.x;
  const int m0 = blockIdx.x * BM;   // m-tile fastest -> both m-tiles of an n-tile adjacent (L2 reuse of B)
  const int n0 = blockIdx.y * BN;
  const int warp = tid >> 5, lane = tid & 31;
  const int wm = (warp >> 1) * 32, wn = (warp & 1) * 32;  // 4x2 warp grid, 32x32 warp tile

  float acc[2][4][4];
#pragma unroll
  for (int i=0;i<2;i++)
#pragma unroll
    for(int j=0;j<4;j++)
#pragma unroll
      for(int k=0;k<4;k++) acc[i][j][k]=0.f;

  const int nch = K / BK;
  load_chunk(bufs[0], Ahi, Alo, B, m0, n0, 0, K, N, tid);
  cp_commit();

  for (int i=0;i<nch;i++){
    if (i+1 < nch){
      load_chunk(bufs[(i+1)&1], Ahi, Alo, B, m0, n0, (i+1)*BK, K, N, tid);
      cp_commit();
      cp_wait<1>();
    } else {
      cp_wait<0>();
    }
    __syncthreads();
    Buf& b = bufs[i&1];
    // convert B f32 -> bf16 hi/lo in smem
#pragma unroll
    for (int c=0;c<8;c++){
      int e = tid + c*256;
      int r = e >> 5, col = e & 31;
      float x = b.Bf[r*BFST + col];
      __nv_bfloat16 h = __float2bfloat16(x);
      __nv_bfloat16 l = __float2bfloat16(x - __bfloat162float(h));
      b.Bhi[r*BST + col] = h;
      b.Blo[r*BST + col] = l;
    }
    __syncthreads();
#pragma unroll
    for (int ks=0; ks<2; ks++){
      const int kk = ks*16;
      uint32_t ahi[2][4], alo[2][4], bhi[4][2], blo[4][2];
      int ar = lane & 15, ac = (lane >> 4) * 8;
#pragma unroll
      for (int ms=0; ms<2; ms++){
        ldsm4(ahi[ms], &b.Ahi[(wm + ms*16 + ar)*AST + kk + ac]);
        ldsm4(alo[ms], &b.Alo[(wm + ms*16 + ar)*AST + kk + ac]);
      }
      int br = lane & 7, bc = ((lane >> 3) & 1) * 8;
#pragma unroll
      for (int ns=0; ns<4; ns++){
        ldsm2(bhi[ns], &b.Bhi[(wn + ns*8 + br)*BST + kk + bc]);
        ldsm2(blo[ns], &b.Blo[(wn + ns*8 + br)*BST + kk + bc]);
      }
#pragma unroll
      for (int ms=0; ms<2; ms++)
#pragma unroll
        for (int ns=0; ns<4; ns++){
          mma_bf16(acc[ms][ns], ahi[ms], bhi[ns]);
          mma_bf16(acc[ms][ns], ahi[ms], blo[ns]);
          mma_bf16(acc[ms][ns], alo[ms], bhi[ns]);
        }
    }
    __syncthreads();
  }

  const int gr = lane >> 2, gc = (lane & 3) * 2;
#pragma unroll
  for (int ms=0; ms<2; ms++)
#pragma unroll
    for (int ns=0; ns<4; ns++){
      int row = m0 + wm + ms*16 + gr;
      int col = n0 + wn + ns*8 + gc;
      if (col < N){   // N%8==0 for all our cases -> pair-safe
        float v0=acc[ms][ns][0], v1=acc[ms][ns][1], v2=acc[ms][ns][2], v3=acc[ms][ns][3];
        if (BIAS){ float c0=bias[col], c1=bias[col+1]; v0+=c0; v1+=c1; v2+=c0; v3+=c1; }
        if (RELU){ v0=fmaxf(v0,0.f); v1=fmaxf(v1,0.f); v2=fmaxf(v2,0.f); v3=fmaxf(v3,0.f); }
        *reinterpret_cast<float2*>(&C[(size_t)row*N + col])     = make_float2(v0,v1);
        *reinterpret_cast<float2*>(&C[(size_t)(row+8)*N + col]) = make_float2(v2,v3);
      }
    }
}

__global__ void split_k(const float* __restrict__ src, __nv_bfloat16* __restrict__ hi,
                        __nv_bfloat16* __restrict__ lo, int n){
  int i = blockIdx.x*256 + threadIdx.x;
  if (i < n){
    float x = src[i];
    __nv_bfloat16 h = __float2bfloat16(x);
    hi[i] = h;
    lo[i] = __float2bfloat16(x - __bfloat162float(h));
  }
}

// per-row L2 normalize, scale by exp(logit_scale), write bf16 hi/lo split
__global__ void rownorm_split(const float* __restrict__ img, const float* __restrict__ ls,
                              __nv_bfloat16* __restrict__ hi, __nv_bfloat16* __restrict__ lo){
  __shared__ float red[128];
  __shared__ float sc_s;
  int row = blockIdx.x, t = threadIdx.x;
  float v[4]; float s = 0.f;
#pragma unroll
  for (int j=0;j<4;j++){ v[j] = img[row*D_OUTF + t + j*128]; s += v[j]*v[j]; }
  red[t] = s; __syncthreads();
  for (int off=64; off>0; off>>=1){ if (t<off) red[t]+=red[t+off]; __syncthreads(); }
  if (t==0) sc_s = expf(*ls) / sqrtf(red[0]);
  __syncthreads();
  float sc = sc_s;
#pragma unroll
  for (int j=0;j<4;j++){
    float x = v[j]*sc;
    __nv_bfloat16 h = __float2bfloat16(x);
    int idx = row*D_OUTF + t + j*128;
    hi[idx] = h;
    lo[idx] = __float2bfloat16(x - __bfloat162float(h));
  }
}

// row-0 softmax stats + top-5 (5 rounds of deterministic block argmax, tie -> lower index)
__global__ void softmax_topk(const float* __restrict__ logits, const float* __restrict__ gps,
                             float* __restrict__ out_tail){
  __shared__ float sVal[1024];
  __shared__ int   sIdx[1024];
  __shared__ float sMax, sSum;
  __shared__ int   fIdx[TOPK];
  __shared__ float fVal[TOPK];
  int t = threadIdx.x;
  float m = -3.4e38f;
  for (int i=t;i<M_GAL;i+=1024) m = fmaxf(m, logits[i]);
  sVal[t]=m; __syncthreads();
  for (int s=512;s>0;s>>=1){ if(t<s) sVal[t]=fmaxf(sVal[t],sVal[t+s]); __syncthreads(); }
  if (t==0) sMax=sVal[0];
  __syncthreads();
  float mx = sMax;
  float sum=0.f;
  for (int i=t;i<M_GAL;i+=1024) sum += expf(logits[i]-mx);
  sVal[t]=sum; __syncthreads();
  for (int s=512;s>0;s>>=1){ if(t<s) sVal[t]+=sVal[t+s]; __syncthreads(); }
  if (t==0) sSum=sVal[0];
  __syncthreads();
  float denom = sSum;
  for (int r=0;r<TOPK;r++){
    float bv=-3.4e38f; int bi=0x7fffffff;
    for (int i=t;i<M_GAL;i+=1024){
      bool skip=false;
#pragma unroll
      for (int j=0;j<TOPK;j++) if (j<r && fIdx[j]==i) skip=true;
      float v = logits[i];
      if (!skip && (v>bv || (v==bv && i<bi))){ bv=v; bi=i; }
    }
    sVal[t]=bv; sIdx[t]=bi; __syncthreads();
    for (int s=512;s>0;s>>=1){
      if (t<s){
        if (sVal[t+s]>sVal[t] || (sVal[t+s]==sVal[t] && sIdx[t+s]<sIdx[t])){
          sVal[t]=sVal[t+s]; sIdx[t]=sIdx[t+s];
        }
      }
      __syncthreads();
    }
    if (t==0){ fIdx[r]=sIdx[0]; fVal[r]=sVal[0]; }
    __syncthreads();
  }
  if (t<TOPK){
    int gi = fIdx[t];
    out_tail[2*t]   = gps[2*gi];
    out_tail[2*t+1] = gps[2*gi+1];
    out_tail[2*TOPK + t] = expf(fVal[t]-mx)/denom;
  }
}

extern "C" void kernel_launch(void* const* d_in, const int* in_sizes, int n_in,
                              void* d_out, int out_size){
  const float* img_feats   = (const float*)d_in[0];
  const float* w1          = (const float*)d_in[1];
  const float* b1          = (const float*)d_in[2];
  const float* w2          = (const float*)d_in[3];
  const float* b2          = (const float*)d_in[4];
  const float* logit_scale = (const float*)d_in[5];
  const float* loc_feats   = (const float*)d_in[6];
  const float* gps         = (const float*)d_in[7];
  float* out = (float*)d_out;

  void *ahi1,*alo1,*h,*ahi2,*alo2,*imgb,*ahin,*alon;
  cudaGetSymbolAddress(&ahi1, g_Ahi1);
  cudaGetSymbolAddress(&alo1, g_Alo1);
  cudaGetSymbolAddress(&h,    g_H);
  cudaGetSymbolAddress(&ahi2, g_Ahi2);
  cudaGetSymbolAddress(&alo2, g_Alo2);
  cudaGetSymbolAddress(&imgb, g_IMG);
  cudaGetSymbolAddress(&ahin, g_AhiN);
  cudaGetSymbolAddress(&alon, g_AloN);

  int smem = (int)(sizeof(Buf)*2);
  cudaFuncSetAttribute(gemm3s<true,true>,   cudaFuncAttributeMaxDynamicSharedMemorySize, smem);
  cudaFuncSetAttribute(gemm3s<true,false>,  cudaFuncAttributeMaxDynamicSharedMemorySize, smem);
  cudaFuncSetAttribute(gemm3s<false,false>, cudaFuncAttributeMaxDynamicSharedMemorySize, smem);

  // 1) split input
  split_k<<<(N_IMG*D_INF+255)/256,256>>>(img_feats, (__nv_bfloat16*)ahi1, (__nv_bfloat16*)alo1, N_IMG*D_INF);
  // 2) H = relu(X W1^T + b1)
  gemm3s<true,true><<<dim3(2, D_HID/BN), 256, smem>>>((__nv_bfloat16*)ahi1,(__nv_bfloat16*)alo1,
                                                      w1, b1, (float*)h, D_HID, D_INF);
  // 3) split H
  split_k<<<(N_IMG*D_HID+255)/256,256>>>((const float*)h, (__nv_bfloat16*)ahi2, (__nv_bfloat16*)alo2, N_IMG*D_HID);
  // 4) IMG = H W2^T + b2
  gemm3s<true,false><<<dim3(2, D_OUTF/BN), 256, smem>>>((__nv_bfloat16*)ahi2,(__nv_bfloat16*)alo2,
                                                        w2, b2, (float*)imgb, D_OUTF, D_HID);
  // 5) normalize rows, fold in exp(logit_scale), split
  rownorm_split<<<N_IMG,128>>>((const float*)imgb, logit_scale, (__nv_bfloat16*)ahin, (__nv_bfloat16*)alon);
  // 6) logits = (s*img_n) loc_feats^T  -> d_out
  gemm3s<false,false><<<dim3(2, (M_GAL+BN-1)/BN), 256, smem>>>((__nv_bfloat16*)ahin,(__nv_bfloat16*)alon,
                                                               loc_feats, nullptr, out, M_GAL, D_OUTF);
  // 7) row-0 softmax + top-5 -> gps + probs tail
  softmax_topk<<<1,1024>>>(out, gps, out + (size_t)N_IMG*M_GAL);
}

// round 3
// speedup vs baseline: 2.2075x; 2.2075x over previous
#include <cuda_runtime.h>
#include <cuda_fp16.h>
#include <cstdint>

#define DEV __device__ __forceinline__

// problem dims
#define N_IMG 256
#define D_INF 768
#define D_HID 768
#define D_OUTF 512
#define M_GAL 100000
#define TOPK 5

// scratch (no cudaMalloc allowed)
__device__ __half g_Ahi1[N_IMG*D_INF];
__device__ __half g_Alo1[N_IMG*D_INF];
__device__ float  g_H   [N_IMG*D_HID];
__device__ __half g_Ahi2[N_IMG*D_HID];
__device__ __half g_Alo2[N_IMG*D_HID];
__device__ float  g_IMG [N_IMG*D_OUTF];
__device__ __half g_AhiN[N_IMG*D_OUTF];
__device__ __half g_AloN[N_IMG*D_OUTF];
// topk scratch
__device__ float g_pmax[100];
__device__ float g_psum[100];
__device__ int   g_pidx[100*TOPK];
__device__ float g_pval[100*TOPK];

DEV void cp16(void* s, const void* g){
  uint32_t sa = (uint32_t)__cvta_generic_to_shared(s);
  asm volatile("cp.async.cg.shared.global [%0], [%1], 16;" :: "r"(sa), "l"(g));
}
DEV void cp_commit(){ asm volatile("cp.async.commit_group;"); }
DEV void cp_wait0(){ asm volatile("cp.async.wait_group 0;"); }

DEV void ldsm4(uint32_t* d, const void* p){
  uint32_t a=(uint32_t)__cvta_generic_to_shared(p);
  asm volatile("ldmatrix.sync.aligned.m8n8.x4.shared.b16 {%0,%1,%2,%3}, [%4];"
    : "=r"(d[0]),"=r"(d[1]),"=r"(d[2]),"=r"(d[3]) : "r"(a));
}
DEV void mma_fp16(float* c, const uint32_t* a, const uint32_t* b){
  asm volatile("mma.sync.aligned.m16n8k16.row.col.f32.f16.f16.f32 "
    "{%0,%1,%2,%3}, {%4,%5,%6,%7}, {%8,%9}, {%0,%1,%2,%3};"
    : "+f"(c[0]),"+f"(c[1]),"+f"(c[2]),"+f"(c[3])
    : "r"(a[0]),"r"(a[1]),"r"(a[2]),"r"(a[3]),"r"(b[0]),"r"(b[1]));
}

// C[Mtot=256, Ntot] = A[.,K] * B[Ntot,K]^T. A pre-split fp16 hi/lo; B f32 converted inline.
// TERMS=2: Ahi*Bh + Alo*Bh (B single fp16). TERMS=3: + Ahi*Bl (B split).
// CTA tile 128 x BN, BK=64, 2-stage cp.async pipeline, warp tile 32x32.
template<int BN, int TERMS, bool BIAS, bool RELU>
__global__ __launch_bounds__(BN*4, 1)
void hgemm(const __half* __restrict__ Ahi, const __half* __restrict__ Alo,
           const float* __restrict__ B, const float* __restrict__ bias,
           float* __restrict__ C, int Ntot, int K){
  constexpr int NT   = BN*4;        // threads: (128/32)*(BN/32) warps
  constexpr int SABB = 144;         // smem row stride bytes (72 halfs), pad kills bank conflicts
  constexpr int ABYTES = 128*SABB;  // one A matrix (hi or lo)
  constexpr int OB     = 2*ABYTES;
  constexpr int BBYTES = BN*SABB;
  constexpr int STAGE  = OB + BBYTES*((TERMS==3)?2:1);
  constexpr int SEGA   = 128*8;     // 16B segments in A tile
  constexpr int SEGB   = BN*8;      // 8-float segments in B tile
  constexpr int APT    = SEGA/NT;
  constexpr int BPT    = SEGB/NT;

  extern __shared__ __align__(16) char sm[];
  const int tid = threadIdx.x, lane = tid & 31, warp = tid >> 5;
  const int wm = (warp & 3) * 32, wn = (warp >> 2) * 32;
  const int m0 = blockIdx.x * 128, n0 = blockIdx.y * BN;
  const int nch = K / 64;

  float acc[2][4][4];
#pragma unroll
  for (int a=0;a<2;a++)
#pragma unroll
    for (int b=0;b<4;b++)
#pragma unroll
      for (int c=0;c<4;c++) acc[a][b][c]=0.f;

  float4 breg[BPT][2];

  auto loadB = [&](int kb){
#pragma unroll
    for (int s=0;s<BPT;s++){
      int seg = tid + s*NT;
      int row = seg >> 3, sc = seg & 7;
      int gn = n0 + row; if (gn > Ntot-1) gn = Ntot-1;
      const float4* p = reinterpret_cast<const float4*>(B + (size_t)gn*K + kb + sc*8);
      breg[s][0] = p[0]; breg[s][1] = p[1];
    }
  };
  auto stsB = [&](int buf){
#pragma unroll
    for (int s=0;s<BPT;s++){
      int seg = tid + s*NT;
      int row = seg >> 3, sc = seg & 7;
      float f[8] = {breg[s][0].x,breg[s][0].y,breg[s][0].z,breg[s][0].w,
                    breg[s][1].x,breg[s][1].y,breg[s][1].z,breg[s][1].w};
      union { uint4 u; __half h[8]; } ph, pl;
#pragma unroll
      for (int e=0;e<8;e++){
        __half hh = __float2half_rn(f[e]);
        ph.h[e] = hh;
        if (TERMS==3) pl.h[e] = __float2half_rn(f[e] - __half2float(hh));
      }
      char* dst = sm + buf*STAGE + OB + row*SABB + sc*16;
      *reinterpret_cast<uint4*>(dst) = ph.u;
      if (TERMS==3) *reinterpret_cast<uint4*>(dst + BBYTES) = pl.u;
    }
  };
  auto cpA = [&](int buf, int kb){
#pragma unroll
    for (int s=0;s<APT;s++){
      int seg = tid + s*NT;
      int row = seg >> 3, sc = seg & 7;
      size_t go = (size_t)(m0 + row)*K + kb + sc*8;
      char* d = sm + buf*STAGE + row*SABB + sc*16;
      cp16(d,          Ahi + go);
      cp16(d + ABYTES, Alo + go);
    }
  };
  auto do_mma = [&](int buf){
    char* sa  = sm + buf*STAGE;
    char* sbh = sa + OB;
    const int ar = lane & 15, ac = (lane >> 4) * 8;
    const int q = lane >> 3, rq = lane & 7;
    const int bro = ((q>>1)*8 + rq)*SABB + (q&1)*16;
#pragma unroll
    for (int ks=0; ks<4; ks++){
      const int kk = ks*16;
      uint32_t ah[2][4], al[2][4], bh[8], bl[8];
#pragma unroll
      for (int ms=0; ms<2; ms++){
        char* pa = sa + (wm + ms*16 + ar)*SABB + (kk + ac)*2;
        ldsm4(ah[ms], pa);
        ldsm4(al[ms], pa + ABYTES);
      }
#pragma unroll
      for (int nsp=0; nsp<2; nsp++){
        char* pb = sbh + (wn + nsp*16)*SABB + kk*2 + bro;
        ldsm4(bh + nsp*4, pb);
        if (TERMS==3) ldsm4(bl + nsp*4, pb + BBYTES);
      }
#pragma unroll
      for (int ms=0; ms<2; ms++)
#pragma unroll
        for (int ns=0; ns<4; ns++) mma_fp16(acc[ms][ns], ah[ms], bh + ns*2);
#pragma unroll
      for (int ms=0; ms<2; ms++)
#pragma unroll
        for (int ns=0; ns<4; ns++) mma_fp16(acc[ms][ns], al[ms], bh + ns*2);
      if (TERMS==3){
#pragma unroll
        for (int ms=0; ms<2; ms++)
#pragma unroll
          for (int ns=0; ns<4; ns++) mma_fp16(acc[ms][ns], ah[ms], bl + ns*2);
      }
    }
  };

  // prologue: chunk 0
  loadB(0);
  stsB(0);
  cpA(0, 0);
  cp_commit();

  for (int i=0; i<nch; i++){
    const int buf = i & 1;
    if (i+1 < nch) loadB((i+1)*64);
    cp_wait0();
    __syncthreads();                 // stage buf ready; all warps done with MMA(i-1)
    if (i+1 < nch){ cpA(buf^1, (i+1)*64); cp_commit(); }
    do_mma(buf);                     // overlaps in-flight cp.async + B LDG returns
    if (i+1 < nch) stsB(buf^1);
  }

  // epilogue: direct stores (frag rows; 4 lanes cover 8 consecutive cols = 32B sectors)
  const int gr = lane >> 2, gc = (lane & 3) * 2;
#pragma unroll
  for (int ms=0; ms<2; ms++)
#pragma unroll
    for (int ns=0; ns<4; ns++){
      int row = m0 + wm + ms*16 + gr;
      int col = n0 + wn + ns*8 + gc;
      if (col < Ntot){
        float v0=acc[ms][ns][0], v1=acc[ms][ns][1], v2=acc[ms][ns][2], v3=acc[ms][ns][3];
        if (BIAS){ float c0=bias[col], c1=bias[col+1]; v0+=c0; v1+=c1; v2+=c0; v3+=c1; }
        if (RELU){ v0=fmaxf(v0,0.f); v1=fmaxf(v1,0.f); v2=fmaxf(v2,0.f); v3=fmaxf(v3,0.f); }
        *reinterpret_cast<float2*>(&C[(size_t)row*Ntot + col])     = make_float2(v0,v1);
        *reinterpret_cast<float2*>(&C[(size_t)(row+8)*Ntot + col]) = make_float2(v2,v3);
      }
    }
}

__global__ void split_k(const float* __restrict__ src, __half* __restrict__ hi,
                        __half* __restrict__ lo, int n){
  int i = blockIdx.x*256 + threadIdx.x;
  if (i < n){
    float x = src[i];
    __half h = __float2half_rn(x);
    hi[i] = h;
    lo[i] = __float2half_rn(x - __half2float(h));
  }
}

// per-row L2 normalize, scale by exp(logit_scale), fp16 hi/lo split
__global__ void rownorm_split(const float* __restrict__ img, const float* __restrict__ ls,
                              __half* __restrict__ hi, __half* __restrict__ lo){
  __shared__ float red[128];
  __shared__ float sc_s;
  int row = blockIdx.x, t = threadIdx.x;
  float v[4]; float s = 0.f;
#pragma unroll
  for (int j=0;j<4;j++){ v[j] = img[row*D_OUTF + t + j*128]; s += v[j]*v[j]; }
  red[t] = s; __syncthreads();
  for (int off=64; off>0; off>>=1){ if (t<off) red[t]+=red[t+off]; __syncthreads(); }
  if (t==0) sc_s = expf(*ls) / sqrtf(red[0]);
  __syncthreads();
  float sc = sc_s;
#pragma unroll
  for (int j=0;j<4;j++){
    float x = v[j]*sc;
    __half h = __float2half_rn(x);
    int idx = row*D_OUTF + t + j*128;
    hi[idx] = h;
    lo[idx] = __float2half_rn(x - __half2float(h));
  }
}

// topk phase 1: 100 blocks x 256 threads over row 0 (1000 logits each)
__global__ void topk_p1(const float* __restrict__ logits){
  __shared__ float rv[256];
  __shared__ int   ri[256];
  __shared__ int   sel[TOPK];
  __shared__ float bmax_s;
  int t = threadIdx.x, b = blockIdx.x;
  int lo = b*1000, hi = lo + 1000;

  float m = -3.4e38f;
  for (int i = lo + t; i < hi; i += 256) m = fmaxf(m, logits[i]);
  rv[t] = m; __syncthreads();
  for (int s=128; s>0; s>>=1){ if (t<s) rv[t]=fmaxf(rv[t],rv[t+s]); __syncthreads(); }
  if (t==0) bmax_s = rv[0];
  __syncthreads();
  float bm = bmax_s;

  float sum = 0.f;
  for (int i = lo + t; i < hi; i += 256) sum += expf(logits[i] - bm);
  rv[t] = sum; __syncthreads();
  for (int s=128; s>0; s>>=1){ if (t<s) rv[t]+=rv[t+s]; __syncthreads(); }
  if (t==0){ g_pmax[b] = bm; g_psum[b] = rv[0]; }
  __syncthreads();

  for (int r = 0; r < TOPK; r++){
    float bv = -3.4e38f; int bi = 0x7fffffff;
    for (int i = lo + t; i < hi; i += 256){
      bool skip = false;
#pragma unroll
      for (int j = 0; j < TOPK; j++) if (j < r && sel[j] == i) skip = true;
      float v = logits[i];
      if (!skip && (v > bv || (v == bv && i < bi))){ bv = v; bi = i; }
    }
    rv[t] = bv; ri[t] = bi; __syncthreads();
    for (int s=128; s>0; s>>=1){
      if (t<s){
        if (rv[t+s] > rv[t] || (rv[t+s] == rv[t] && ri[t+s] < ri[t])){
          rv[t]=rv[t+s]; ri[t]=ri[t+s];
        }
      }
      __syncthreads();
    }
    if (t==0){ sel[r] = ri[0]; g_pidx[b*TOPK + r] = ri[0]; g_pval[b*TOPK + r] = rv[0]; }
    __syncthreads();
  }
}

// topk phase 2: merge 100 partials, write gps + probs tail
__global__ void topk_p2(const float* __restrict__ gps, float* __restrict__ out_tail){
  __shared__ float rv[512];
  __shared__ int   ri[512];
  __shared__ float gM_s, gS_s;
  int t = threadIdx.x;

  float m = (t < 100) ? g_pmax[t] : -3.4e38f;
  rv[t] = m; __syncthreads();
  for (int s=256; s>0; s>>=1){ if (t<s) rv[t]=fmaxf(rv[t],rv[t+s]); __syncthreads(); }
  if (t==0) gM_s = rv[0];
  __syncthreads();
  float M = gM_s;

  float sum = (t < 100) ? g_psum[t] * expf(g_pmax[t] - M) : 0.f;
  rv[t] = sum; __syncthreads();
  for (int s=256; s>0; s>>=1){ if (t<s) rv[t]+=rv[t+s]; __syncthreads(); }
  if (t==0) gS_s = rv[0];
  __syncthreads();
  float S = gS_s;

  float cv = (t < 100*TOPK) ? g_pval[t] : -3.4e38f;
  int   ci = (t < 100*TOPK) ? g_pidx[t] : 0x7fffffff;

  for (int r = 0; r < TOPK; r++){
    rv[t] = cv; ri[t] = ci; __syncthreads();
    for (int s=256; s>0; s>>=1){
      if (t<s){
        if (rv[t+s] > rv[t] || (rv[t+s] == rv[t] && ri[t+s] < ri[t])){
          rv[t]=rv[t+s]; ri[t]=ri[t+s];
        }
      }
      __syncthreads();
    }
    if (t == 0){
      int gi = ri[0];
      out_tail[2*r]   = gps[2*gi];
      out_tail[2*r+1] = gps[2*gi+1];
      out_tail[2*TOPK + r] = expf(rv[0] - M) / S;
    }
    __syncthreads();
    if (ci == ri[0]) cv = -3.4e38f;   // winner indices are unique
    __syncthreads();
  }
}

extern "C" void kernel_launch(void* const* d_in, const int* in_sizes, int n_in,
                              void* d_out, int out_size){
  const float* img_feats   = (const float*)d_in[0];
  const float* w1          = (const float*)d_in[1];
  const float* b1          = (const float*)d_in[2];
  const float* w2          = (const float*)d_in[3];
  const float* b2          = (const float*)d_in[4];
  const float* logit_scale = (const float*)d_in[5];
  const float* loc_feats   = (const float*)d_in[6];
  const float* gps         = (const float*)d_in[7];
  float* out = (float*)d_out;

  void *ahi1,*alo1,*h,*ahi2,*alo2,*imgb,*ahin,*alon;
  cudaGetSymbolAddress(&ahi1, g_Ahi1);
  cudaGetSymbolAddress(&alo1, g_Alo1);
  cudaGetSymbolAddress(&h,    g_H);
  cudaGetSymbolAddress(&ahi2, g_Ahi2);
  cudaGetSymbolAddress(&alo2, g_Alo2);
  cudaGetSymbolAddress(&imgb, g_IMG);
  cudaGetSymbolAddress(&ahin, g_AhiN);
  cudaGetSymbolAddress(&alon, g_AloN);

  // dyn smem: 2 stages; both instantiations total 110592 bytes
  cudaFuncSetAttribute(hgemm<64,3,true,true>,    cudaFuncAttributeMaxDynamicSharedMemorySize, 110592);
  cudaFuncSetAttribute(hgemm<64,3,true,false>,   cudaFuncAttributeMaxDynamicSharedMemorySize, 110592);
  cudaFuncSetAttribute(hgemm<128,2,false,false>, cudaFuncAttributeMaxDynamicSharedMemorySize, 110592);

  // 1) split input to fp16 hi/lo
  split_k<<<(N_IMG*D_INF+255)/256,256>>>(img_feats, (__half*)ahi1, (__half*)alo1, N_IMG*D_INF);
  // 2) H = relu(X W1^T + b1)   (3-term fp16: error ~2^-22)
  hgemm<64,3,true,true><<<dim3(2, D_HID/64), 256, 110592>>>(
      (__half*)ahi1, (__half*)alo1, w1, b1, (float*)h, D_HID, D_INF);
  // 3) split H
  split_k<<<(N_IMG*D_HID+255)/256,256>>>((const float*)h, (__half*)ahi2, (__half*)alo2, N_IMG*D_HID);
  // 4) IMG = H W2^T + b2
  hgemm<64,3,true,false><<<dim3(2, D_OUTF/64), 256, 110592>>>(
      (__half*)ahi2, (__half*)alo2, w2, b2, (float*)imgb, D_OUTF, D_HID);
  // 5) normalize rows, fold in exp(logit_scale), split
  rownorm_split<<<N_IMG,128>>>((const float*)imgb, logit_scale, (__half*)ahin, (__half*)alon);
  // 6) logits = (s*img_n) loc_feats^T  (2-term fp16)
  hgemm<128,2,false,false><<<dim3(2, (M_GAL+127)/128), 512, 110592>>>(
      (__half*)ahin, (__half*)alon, loc_feats, nullptr, out, M_GAL, D_OUTF);
  // 7) row-0 softmax + top-5
  topk_p1<<<100,256>>>(out);
  topk_p2<<<1,512>>>(gps, out + (size_t)N_IMG*M_GAL);
}

// round 5
// speedup vs baseline: 2.8648x; 1.2978x over previous
#include <cuda_runtime.h>
#include <cuda_fp16.h>
#include <cstdint>

#define DEV __device__ __forceinline__

// problem dims
#define N_IMG 256
#define D_INF 768
#define D_HID 768
#define D_OUTF 512
#define M_GAL 100000
#define TOPK 5

// scratch (no cudaMalloc allowed)
__device__ __half g_Ahi1[N_IMG*D_INF];
__device__ __half g_Alo1[N_IMG*D_INF];
__device__ __half g_Ahi2[N_IMG*D_HID];
__device__ __half g_Alo2[N_IMG*D_HID];
__device__ float  g_IMG [N_IMG*D_OUTF];
__device__ __half g_AN  [N_IMG*D_OUTF];
__device__ __half g_Bh  [(size_t)M_GAL*D_OUTF];   // fp16 gallery (prepass)
// topk scratch
__device__ float g_pmax[100];
__device__ float g_psum[100];
__device__ int   g_pidx[100*TOPK];
__device__ float g_pval[100*TOPK];

DEV void cp16(void* s, const void* g){
  uint32_t sa = (uint32_t)__cvta_generic_to_shared(s);
  asm volatile("cp.async.cg.shared.global [%0], [%1], 16;" :: "r"(sa), "l"(g));
}
DEV void cp_commit(){ asm volatile("cp.async.commit_group;"); }
DEV void cp_wait0(){ asm volatile("cp.async.wait_group 0;"); }
DEV void cp_wait1(){ asm volatile("cp.async.wait_group 1;"); }

DEV void ldsm4(uint32_t* d, const void* p){
  uint32_t a=(uint32_t)__cvta_generic_to_shared(p);
  asm volatile("ldmatrix.sync.aligned.m8n8.x4.shared.b16 {%0,%1,%2,%3}, [%4];"
    : "=r"(d[0]),"=r"(d[1]),"=r"(d[2]),"=r"(d[3]) : "r"(a));
}
DEV void mma_fp16(float* c, const uint32_t* a, const uint32_t* b){
  asm volatile("mma.sync.aligned.m16n8k16.row.col.f32.f16.f16.f32 "
    "{%0,%1,%2,%3}, {%4,%5,%6,%7}, {%8,%9}, {%0,%1,%2,%3};"
    : "+f"(c[0]),"+f"(c[1]),"+f"(c[2]),"+f"(c[3])
    : "r"(a[0]),"r"(a[1]),"r"(a[2]),"r"(a[3]),"r"(b[0]),"r"(b[1]));
}

// ---------------- prepass: f32 -> fp16 (8 elems / thread) ----------------
__global__ void convB(const float* __restrict__ src, __half* __restrict__ dst, int n8){
  int i = blockIdx.x*256 + threadIdx.x;
  if (i < n8){
    const float4* p = reinterpret_cast<const float4*>(src) + (size_t)i*2;
    float4 a = p[0], b = p[1];
    union { uint4 u; __half2 h[4]; } o;
    o.h[0] = __floats2half2_rn(a.x, a.y);
    o.h[1] = __floats2half2_rn(a.z, a.w);
    o.h[2] = __floats2half2_rn(b.x, b.y);
    o.h[3] = __floats2half2_rn(b.z, b.w);
    reinterpret_cast<uint4*>(dst)[i] = o.u;
  }
}

// ---------------- MLP GEMM: 3-term fp16, BM=64 BN=64 BK=64, 256 thr ----------------
// C = A[64-rows tile, K] * B[Ntot,K]^T ; A split fp16 hi/lo; B f32 register-staged.
template<bool RELU, bool SPLIT>
__global__ __launch_bounds__(256, 2)
void hgemm3(const __half* __restrict__ Ahi, const __half* __restrict__ Alo,
            const float* __restrict__ B, const float* __restrict__ bias,
            float* __restrict__ Cf, __half* __restrict__ Chi, __half* __restrict__ Clo,
            int Ntot, int K){
  constexpr int SABB = 144;
  constexpr int ABYTES = 64*SABB;              // 9216
  constexpr int OB     = 2*ABYTES;             // Bh offset
  constexpr int BBYTES = 64*SABB;
  constexpr int STAGE  = OB + 2*BBYTES;        // 36864

  extern __shared__ __align__(16) char sm[];
  const int tid = threadIdx.x, lane = tid & 31, warp = tid >> 5;
  const int wm = (warp & 1) * 32, wn = (warp >> 1) * 16;   // warp tile 32x16
  const int m0 = blockIdx.x * 64, n0 = blockIdx.y * 64;
  const int nch = K / 64;

  float acc[2][2][4];
#pragma unroll
  for (int a=0;a<2;a++)
#pragma unroll
    for (int b=0;b<2;b++)
#pragma unroll
      for (int c=0;c<4;c++) acc[a][b][c]=0.f;

  float4 breg[2][2];
  auto loadB = [&](int kb){
#pragma unroll
    for (int s=0;s<2;s++){
      int seg = tid + s*256;                 // 512 segs of 8 f32
      int row = seg >> 3, sc = seg & 7;
      const float4* p = reinterpret_cast<const float4*>(B + (size_t)(n0+row)*K + kb + sc*8);
      breg[s][0] = p[0]; breg[s][1] = p[1];
    }
  };
  auto stsB = [&](int buf){
#pragma unroll
    for (int s=0;s<2;s++){
      int seg = tid + s*256;
      int row = seg >> 3, sc = seg & 7;
      float f[8] = {breg[s][0].x,breg[s][0].y,breg[s][0].z,breg[s][0].w,
                    breg[s][1].x,breg[s][1].y,breg[s][1].z,breg[s][1].w};
      union { uint4 u; __half h[8]; } ph, pl;
#pragma unroll
      for (int e=0;e<8;e++){
        __half hh = __float2half_rn(f[e]);
        ph.h[e] = hh;
        pl.h[e] = __float2half_rn(f[e] - __half2float(hh));
      }
      char* dst = sm + buf*STAGE + OB + row*SABB + sc*16;
      *reinterpret_cast<uint4*>(dst)          = ph.u;
      *reinterpret_cast<uint4*>(dst + BBYTES) = pl.u;
    }
  };
  auto cpA = [&](int buf, int kb){
#pragma unroll
    for (int s=0;s<2;s++){
      int seg = tid + s*256;
      int row = seg >> 3, sc = seg & 7;
      size_t go = (size_t)(m0 + row)*K + kb + sc*8;
      char* d = sm + buf*STAGE + row*SABB + sc*16;
      cp16(d,          Ahi + go);
      cp16(d + ABYTES, Alo + go);
    }
  };
  auto do_mma = [&](int buf){
    char* sa  = sm + buf*STAGE;
    char* sbh = sa + OB;
    const int ar = lane & 15, ac = (lane >> 4) * 8;
    const int q = lane >> 3, rq = lane & 7;
    const int bro = ((q>>1)*8 + rq)*SABB + (q&1)*16;
#pragma unroll
    for (int ks=0; ks<4; ks++){
      const int kk = ks*16;
      uint32_t ah[2][4], al[2][4], bh[4], bl[4];
#pragma unroll
      for (int ms=0; ms<2; ms++){
        char* pa = sa + (wm + ms*16 + ar)*SABB + (kk + ac)*2;
        ldsm4(ah[ms], pa);
        ldsm4(al[ms], pa + ABYTES);
      }
      {
        char* pb = sbh + wn*SABB + kk*2 + bro;
        ldsm4(bh, pb);
        ldsm4(bl, pb + BBYTES);
      }
#pragma unroll
      for (int ms=0; ms<2; ms++)
#pragma unroll
        for (int ns=0; ns<2; ns++){
          mma_fp16(acc[ms][ns], ah[ms], bh + ns*2);
          mma_fp16(acc[ms][ns], al[ms], bh + ns*2);
          mma_fp16(acc[ms][ns], ah[ms], bl + ns*2);
        }
    }
  };

  loadB(0); stsB(0); cpA(0,0); cp_commit();
  for (int i=0; i<nch; i++){
    const int buf = i & 1;
    if (i+1 < nch) loadB((i+1)*64);
    cp_wait0();
    __syncthreads();
    if (i+1 < nch){ cpA(buf^1, (i+1)*64); cp_commit(); }
    do_mma(buf);
    if (i+1 < nch) stsB(buf^1);
  }

  const int gr = lane >> 2, gc = (lane & 3) * 2;
#pragma unroll
  for (int ms=0; ms<2; ms++)
#pragma unroll
    for (int ns=0; ns<2; ns++){
      int row = m0 + wm + ms*16 + gr;
      int col = n0 + wn + ns*8 + gc;
      float v0=acc[ms][ns][0], v1=acc[ms][ns][1], v2=acc[ms][ns][2], v3=acc[ms][ns][3];
      float c0=bias[col], c1=bias[col+1];
      v0+=c0; v1+=c1; v2+=c0; v3+=c1;
      if (RELU){ v0=fmaxf(v0,0.f); v1=fmaxf(v1,0.f); v2=fmaxf(v2,0.f); v3=fmaxf(v3,0.f); }
      if (SPLIT){
        __half h0=__float2half_rn(v0), h1=__float2half_rn(v1);
        __half h2=__float2half_rn(v2), h3=__float2half_rn(v3);
        *reinterpret_cast<__half2*>(&Chi[(size_t)row*Ntot + col])     = __halves2half2(h0,h1);
        *reinterpret_cast<__half2*>(&Chi[(size_t)(row+8)*Ntot + col]) = __halves2half2(h2,h3);
        *reinterpret_cast<__half2*>(&Clo[(size_t)row*Ntot + col]) =
            __halves2half2(__float2half_rn(v0-__half2float(h0)), __float2half_rn(v1-__half2float(h1)));
        *reinterpret_cast<__half2*>(&Clo[(size_t)(row+8)*Ntot + col]) =
            __halves2half2(__float2half_rn(v2-__half2float(h2)), __float2half_rn(v3-__half2float(h3)));
      } else {
        *reinterpret_cast<float2*>(&Cf[(size_t)row*Ntot + col])     = make_float2(v0,v1);
        *reinterpret_cast<float2*>(&Cf[(size_t)(row+8)*Ntot + col]) = make_float2(v2,v3);
      }
    }
}

// ---------------- big GEMM: 1-term pure fp16, BM=128 BN=128 BK=64, 256 thr, 2 CTA/SM ----------------
__global__ __launch_bounds__(256, 2)
void hgemm1(const __half* __restrict__ A, const __half* __restrict__ B,
            float* __restrict__ C, int Ntot, int K){
  constexpr int SABB = 144;
  constexpr int ABYTES = 128*SABB;             // 18432
  constexpr int STAGE  = 2*ABYTES;             // A then B : 36864

  extern __shared__ __align__(16) char sm[];
  const int tid = threadIdx.x, lane = tid & 31, warp = tid >> 5;
  const int wm = (warp & 1) * 64, wn = (warp >> 1) * 32;   // warp tile 64x32
  const int m0 = blockIdx.x * 128, n0 = blockIdx.y * 128;
  const int nch = K / 64;                       // 8

  float acc[4][4][4];
#pragma unroll
  for (int a=0;a<4;a++)
#pragma unroll
    for (int b=0;b<4;b++)
#pragma unroll
      for (int c=0;c<4;c++) acc[a][b][c]=0.f;

  auto issue = [&](int buf, int kb){
#pragma unroll
    for (int s=0;s<4;s++){
      int seg = tid + s*256;                    // 1024 segs of 8 halfs
      int row = seg >> 3, sc = seg & 7;
      char* base = sm + buf*STAGE + row*SABB + sc*16;
      cp16(base, A + (size_t)(m0 + row)*K + kb + sc*8);
      int gn = n0 + row; if (gn > Ntot-1) gn = Ntot-1;
      cp16(base + ABYTES, B + (size_t)gn*K + kb + sc*8);
    }
    cp_commit();
  };
  auto do_mma = [&](int buf){
    char* sa = sm + buf*STAGE;
    char* sb = sa + ABYTES;
    const int ar = lane & 15, ac = (lane >> 4) * 8;
    const int q = lane >> 3, rq = lane & 7;
    const int bro = ((q>>1)*8 + rq)*SABB + (q&1)*16;
#pragma unroll
    for (int ks=0; ks<4; ks++){
      const int kk = ks*16;
      uint32_t af[4][4], bf[8];
#pragma unroll
      for (int ms=0; ms<4; ms++)
        ldsm4(af[ms], sa + (wm + ms*16 + ar)*SABB + (kk + ac)*2);
#pragma unroll
      for (int nsp=0; nsp<2; nsp++)
        ldsm4(bf + nsp*4, sb + (wn + nsp*16)*SABB + kk*2 + bro);
#pragma unroll
      for (int ms=0; ms<4; ms++)
#pragma unroll
        for (int ns=0; ns<4; ns++)
          mma_fp16(acc[ms][ns], af[ms], bf + ns*2);
    }
  };

  issue(0, 0);
  issue(1, 64);
  for (int i=0; i<nch; i++){
    const int buf = i & 1;
    // Need group i complete before reading buf. Groups issued: min(i+2, nch).
    // For i < nch-1 one more group may remain in flight (wait_group 1);
    // at the FINAL iteration nothing else is pending, so wait_group 1 would
    // return without draining group i -> must wait_group 0. (Round-4 bug.)
    if (i == nch-1) cp_wait0(); else cp_wait1();
    __syncthreads();
    do_mma(buf);
    __syncthreads();                    // all warps done reading buf before refill
    if (i+2 < nch) issue(buf, (i+2)*64);
  }

  const int gr = lane >> 2, gc = (lane & 3) * 2;
#pragma unroll
  for (int ms=0; ms<4; ms++)
#pragma unroll
    for (int ns=0; ns<4; ns++){
      int row = m0 + wm + ms*16 + gr;
      int col = n0 + wn + ns*8 + gc;
      if (col < Ntot){
        *reinterpret_cast<float2*>(&C[(size_t)row*Ntot + col])     = make_float2(acc[ms][ns][0], acc[ms][ns][1]);
        *reinterpret_cast<float2*>(&C[(size_t)(row+8)*Ntot + col]) = make_float2(acc[ms][ns][2], acc[ms][ns][3]);
      }
    }
}

// ---------------- small kernels ----------------
__global__ void split_k(const float* __restrict__ src, __half* __restrict__ hi,
                        __half* __restrict__ lo, int n){
  int i = blockIdx.x*256 + threadIdx.x;
  if (i < n){
    float x = src[i];
    __half h = __float2half_rn(x);
    hi[i] = h;
    lo[i] = __float2half_rn(x - __half2float(h));
  }
}

// per-row L2 normalize, scale by exp(logit_scale), single fp16
__global__ void rownorm_h(const float* __restrict__ img, const float* __restrict__ ls,
                          __half* __restrict__ outh){
  __shared__ float red[128];
  __shared__ float sc_s;
  int row = blockIdx.x, t = threadIdx.x;
  float v[4]; float s = 0.f;
#pragma unroll
  for (int j=0;j<4;j++){ v[j] = img[row*D_OUTF + t + j*128]; s += v[j]*v[j]; }
  red[t] = s; __syncthreads();
  for (int off=64; off>0; off>>=1){ if (t<off) red[t]+=red[t+off]; __syncthreads(); }
  if (t==0) sc_s = expf(*ls) / sqrtf(red[0]);
  __syncthreads();
  float sc = sc_s;
#pragma unroll
  for (int j=0;j<4;j++)
    outh[row*D_OUTF + t + j*128] = __float2half_rn(v[j]*sc);
}

// topk phase 1: 100 blocks x 256 threads over row 0 (1000 logits each)
__global__ void topk_p1(const float* __restrict__ logits){
  __shared__ float rv[256];
  __shared__ int   ri[256];
  __shared__ int   sel[TOPK];
  __shared__ float bmax_s;
  int t = threadIdx.x, b = blockIdx.x;
  int lo = b*1000, hi = lo + 1000;

  float m = -3.4e38f;
  for (int i = lo + t; i < hi; i += 256) m = fmaxf(m, logits[i]);
  rv[t] = m; __syncthreads();
  for (int s=128; s>0; s>>=1){ if (t<s) rv[t]=fmaxf(rv[t],rv[t+s]); __syncthreads(); }
  if (t==0) bmax_s = rv[0];
  __syncthreads();
  float bm = bmax_s;

  float sum = 0.f;
  for (int i = lo + t; i < hi; i += 256) sum += expf(logits[i] - bm);
  rv[t] = sum; __syncthreads();
  for (int s=128; s>0; s>>=1){ if (t<s) rv[t]+=rv[t+s]; __syncthreads(); }
  if (t==0){ g_pmax[b] = bm; g_psum[b] = rv[0]; }
  __syncthreads();

  for (int r = 0; r < TOPK; r++){
    float bv = -3.4e38f; int bi = 0x7fffffff;
    for (int i = lo + t; i < hi; i += 256){
      bool skip = false;
#pragma unroll
      for (int j = 0; j < TOPK; j++) if (j < r && sel[j] == i) skip = true;
      float v = logits[i];
      if (!skip && (v > bv || (v == bv && i < bi))){ bv = v; bi = i; }
    }
    rv[t] = bv; ri[t] = bi; __syncthreads();
    for (int s=128; s>0; s>>=1){
      if (t<s){
        if (rv[t+s] > rv[t] || (rv[t+s] == rv[t] && ri[t+s] < ri[t])){
          rv[t]=rv[t+s]; ri[t]=ri[t+s];
        }
      }
      __syncthreads();
    }
    if (t==0){ sel[r] = ri[0]; g_pidx[b*TOPK + r] = ri[0]; g_pval[b*TOPK + r] = rv[0]; }
    __syncthreads();
  }
}

// topk phase 2: merge 100 partials, write gps + probs tail
__global__ void topk_p2(const float* __restrict__ gps, float* __restrict__ out_tail){
  __shared__ float rv[512];
  __shared__ int   ri[512];
  __shared__ float gM_s, gS_s;
  int t = threadIdx.x;

  float m = (t < 100) ? g_pmax[t] : -3.4e38f;
  rv[t] = m; __syncthreads();
  for (int s=256; s>0; s>>=1){ if (t<s) rv[t]=fmaxf(rv[t],rv[t+s]); __syncthreads(); }
  if (t==0) gM_s = rv[0];
  __syncthreads();
  float M = gM_s;

  float sum = (t < 100) ? g_psum[t] * expf(g_pmax[t] - M) : 0.f;
  rv[t] = sum; __syncthreads();
  for (int s=256; s>0; s>>=1){ if (t<s) rv[t]+=rv[t+s]; __syncthreads(); }
  if (t==0) gS_s = rv[0];
  __syncthreads();
  float S = gS_s;

  float cv = (t < 100*TOPK) ? g_pval[t] : -3.4e38f;
  int   ci = (t < 100*TOPK) ? g_pidx[t] : 0x7fffffff;

  for (int r = 0; r < TOPK; r++){
    rv[t] = cv; ri[t] = ci; __syncthreads();
    for (int s=256; s>0; s>>=1){
      if (t<s){
        if (rv[t+s] > rv[t] || (rv[t+s] == rv[t] && ri[t+s] < ri[t])){
          rv[t]=rv[t+s]; ri[t]=ri[t+s];
        }
      }
      __syncthreads();
    }
    if (t == 0){
      int gi = ri[0];
      out_tail[2*r]   = gps[2*gi];
      out_tail[2*r+1] = gps[2*gi+1];
      out_tail[2*TOPK + r] = expf(rv[0] - M) / S;
    }
    __syncthreads();
    if (ci == ri[0]) cv = -3.4e38f;   // winner indices are unique
    __syncthreads();
  }
}

extern "C" void kernel_launch(void* const* d_in, const int* in_sizes, int n_in,
                              void* d_out, int out_size){
  const float* img_feats   = (const float*)d_in[0];
  const float* w1          = (const float*)d_in[1];
  const float* b1          = (const float*)d_in[2];
  const float* w2          = (const float*)d_in[3];
  const float* b2          = (const float*)d_in[4];
  const float* logit_scale = (const float*)d_in[5];
  const float* loc_feats   = (const float*)d_in[6];
  const float* gps         = (const float*)d_in[7];
  float* out = (float*)d_out;

  void *ahi1,*alo1,*ahi2,*alo2,*imgb,*an,*bh;
  cudaGetSymbolAddress(&ahi1, g_Ahi1);
  cudaGetSymbolAddress(&alo1, g_Alo1);
  cudaGetSymbolAddress(&ahi2, g_Ahi2);
  cudaGetSymbolAddress(&alo2, g_Alo2);
  cudaGetSymbolAddress(&imgb, g_IMG);
  cudaGetSymbolAddress(&an,   g_AN);
  cudaGetSymbolAddress(&bh,   g_Bh);

  cudaFuncSetAttribute(hgemm3<true,true>,   cudaFuncAttributeMaxDynamicSharedMemorySize, 73728);
  cudaFuncSetAttribute(hgemm3<false,false>, cudaFuncAttributeMaxDynamicSharedMemorySize, 73728);
  cudaFuncSetAttribute(hgemm1,              cudaFuncAttributeMaxDynamicSharedMemorySize, 73728);

  // 0) prepass: gallery f32 -> fp16
  convB<<<(M_GAL*D_OUTF/8 + 255)/256, 256>>>(loc_feats, (__half*)bh, M_GAL*D_OUTF/8);
  // 1) split input to fp16 hi/lo
  split_k<<<(N_IMG*D_INF+255)/256,256>>>(img_feats, (__half*)ahi1, (__half*)alo1, N_IMG*D_INF);
  // 2) H = relu(X W1^T + b1), epilogue writes fp16 hi/lo split directly
  hgemm3<true,true><<<dim3(4, D_HID/64), 256, 73728>>>(
      (__half*)ahi1, (__half*)alo1, w1, b1, nullptr, (__half*)ahi2, (__half*)alo2, D_HID, D_INF);
  // 3) IMG = H W2^T + b2 (f32 out)
  hgemm3<false,false><<<dim3(4, D_OUTF/64), 256, 73728>>>(
      (__half*)ahi2, (__half*)alo2, w2, b2, (float*)imgb, nullptr, nullptr, D_OUTF, D_HID);
  // 4) normalize rows, fold in exp(logit_scale) -> single fp16
  rownorm_h<<<N_IMG,128>>>((const float*)imgb, logit_scale, (__half*)an);
  // 5) logits = (s*img_n) @ gallery^T  (pure fp16 x fp16)
  hgemm1<<<dim3(2, (M_GAL+127)/128), 256, 73728>>>(
      (__half*)an, (__half*)bh, out, M_GAL, D_OUTF);
  // 6) row-0 softmax + top-5
  topk_p1<<<100,256>>>(out);
  topk_p2<<<1,512>>>(gps, out + (size_t)N_IMG*M_GAL);
}